// round 11
// baseline (speedup 1.0000x reference)
#include <cuda_runtime.h>
#include <cuda_fp16.h>
#include <math_constants.h>
#include <cstdint>

// Max-plus conv2d in fp16x2. out[b,o,h,w] = max_{c,ki,kj} x[...]+k[...]
// B=8, C=64, H=W=64, O=64, 3x3, stride 1, pad 1 (-inf).
//
// Thread tile 8o x 4w x 1h (16 half2 accs) to amortize x-row LDS/PRMT over 2x
// arithmetic: per (cl,ki) = 3 LDS + 3 PRMT + 6 k-LDS.128 per 96 packed arith.
// Block 64 thr = 16 wq x 4 hl, covers 8o x 4h x 64w. Grid = 16ht x 8ot x 8b
// = 1024 (balanced ~7 CTA/SM). CCH=8 chunks, x double-buffered via
// LDG->regs->(cvt+STS after compute). k staged once as (k,k) half2 in
// [c][ki][tap][oo*8] order -> broadcast LDS.128.

constexpr int Cc  = 64;
constexpr int Hc  = 64;
constexpr int Wc  = 64;
constexpr int Oc  = 64;
constexpr int OT  = 8;
constexpr int HT  = 4;
constexpr int CCH = 8;
constexpr int NCH = Cc / CCH;              // 8 chunks
constexpr int XROWS = HT + 2;              // 6
constexpr int HR    = 72;                  // halves per row; col j = w + 4
constexpr int XBUFH = CCH * XROWS * HR;    // 3456 halves per buffer
constexpr int SKH   = Cc * 9 * OT;         // 4608 half2 (dup'd taps)
constexpr int NST   = 12;                  // staging float4 per thread per chunk

__device__ __forceinline__ __half2 u2h(uint32_t u) {
    return *reinterpret_cast<__half2*>(&u);
}

__global__ __launch_bounds__(64)
void maxplus_fp16_kernel(const float* __restrict__ x,
                         const float* __restrict__ gk,
                         float* __restrict__ out)
{
    __shared__ __align__(16) __half  sx[2 * XBUFH];   // 13.8 KB
    __shared__ __align__(16) __half2 sk2[SKH];        // 18.4 KB

    const int bid = blockIdx.x;
    const int ht  = bid & 15;         // 16 h-tiles
    const int ot  = (bid >> 4) & 7;   // 8 o-tiles
    const int b   = bid >> 7;         // 8 batches

    const int h_base = ht * HT;
    const int o_base = ot * OT;

    const int tid = threadIdx.x;      // 0..63
    const int wq  = tid & 15;
    const int hl  = tid >> 4;         // 0..3
    const int wb  = wq * 4;
    const int h   = h_base + hl;

    const __half2 NEG2 = __half2half2(__float2half(-CUDART_INF_F));

    // ---- stage k taps once, duplicated: sk2[(c*9+ki*3+tap)*8+oo] = (k,k) ----
    for (int idx = tid; idx < SKH; idx += 64) {
        int oo   = idx & 7;
        int rest = idx >> 3;          // c*9 + ki*3 + tap
        sk2[idx] = __half2half2(__float2half_rn(gk[(o_base + oo) * (Cc * 9) + rest]));
    }

    // ---- prefill column pads (j=0..3 and 68..71), all rows, both buffers ----
    for (int rw = tid; rw < 2 * CCH * XROWS; rw += 64) {
        __half2* p = reinterpret_cast<__half2*>(sx + rw * HR);
        p[0] = NEG2; p[1] = NEG2;                 // j 0..3
        __half2* q = reinterpret_cast<__half2*>(sx + rw * HR + 68);
        q[0] = NEG2; q[1] = NEG2;                 // j 68..71
    }

    // ---- staging geometry: idx = tid + 64*jj, jj=0..11 covers 768 float4 ----
    const float* xb_base = x + (size_t)b * Cc * Hc * Wc;
    int  gof[NST];    // float offset within a chunk's channel block
    int  dof[NST];    // halves offset within a buffer
    bool vr[NST];
#pragma unroll
    for (int jj = 0; jj < NST; jj++) {
        int idx = tid + 64 * jj;
        int q4  = idx & 15;
        int rw  = idx >> 4;           // cl*6 + r, 0..47
        int r   = rw % XROWS;
        int cl  = rw / XROWS;
        int hh  = h_base - 1 + r;
        vr[jj]  = (hh >= 0 && hh < Hc);
        gof[jj] = (cl * Hc + (vr[jj] ? hh : 0)) * Wc + q4 * 4;
        dof[jj] = rw * HR + 4 + q4 * 4;
    }

    auto stage_sts = [&](const float4* g, int bf) {
#pragma unroll
        for (int jj = 0; jj < NST; jj++) {
            __half2 lo, hi;
            if (vr[jj]) {
                lo = __floats2half2_rn(g[jj].x, g[jj].y);
                hi = __floats2half2_rn(g[jj].z, g[jj].w);
            } else {
                lo = NEG2; hi = NEG2;     // invalid h rows -> -inf
            }
            __half2* p = reinterpret_cast<__half2*>(sx + bf * XBUFH + dof[jj]);
            p[0] = lo; p[1] = hi;
        }
    };

    // accumulators: acc0[oo]=(wb,wb+1), acc1[oo]=(wb+2,wb+3)
    __half2 acc0[OT], acc1[OT];
#pragma unroll
    for (int oo = 0; oo < OT; oo++) { acc0[oo] = NEG2; acc1[oo] = NEG2; }

    // ---- prologue: stage chunk 0 into buffer 0 ----
    {
        float4 g[NST];
#pragma unroll
        for (int jj = 0; jj < NST; jj++)
            if (vr[jj]) g[jj] = *(const float4*)(xb_base + gof[jj]);
        stage_sts(g, 0);
    }

#pragma unroll 1
    for (int ch = 0; ch < NCH; ch++) {
        const int bf = ch & 1;
        float4 g[NST];
        const bool have = (ch + 1 < NCH);
        if (have) {
            const float* src = xb_base + (size_t)(ch + 1) * CCH * Hc * Wc;
#pragma unroll
            for (int jj = 0; jj < NST; jj++)
                if (vr[jj]) g[jj] = *(const float4*)(src + gof[jj]);
        }
        __syncthreads();   // chunk ch staged (prev iter / prologue)

        // ---- compute chunk ch from buffer bf ----
        const __half* xb = sx + bf * XBUFH;
#pragma unroll 2
        for (int cl = 0; cl < CCH; cl++) {
            const int cg = ch * CCH + cl;
#pragma unroll
            for (int ki = 0; ki < 3; ki++) {
                const __half* row = xb + (cl * XROWS + hl + ki) * HR;
                uint2    Eu = *(const uint2*)(row + wb + 4);
                uint32_t Mu = *(const uint32_t*)(row + wb + 2);
                uint32_t Nu = *(const uint32_t*)(row + wb + 8);
                uint32_t O0u = __byte_perm(Mu,   Eu.x, 0x5432); // (x[wb-1],x[wb])
                uint32_t O1u = __byte_perm(Eu.x, Eu.y, 0x5432); // (x[wb+1],x[wb+2])
                uint32_t O2u = __byte_perm(Eu.y, Nu,   0x5432); // (x[wb+3],x[wb+4])
                __half2 E0 = u2h(Eu.x), E1 = u2h(Eu.y);
                __half2 O0 = u2h(O0u), O1 = u2h(O1u), O2 = u2h(O2u);

                // k: uint4 index = (cg*9+ki*3+tap)*2 + gg  (gg = oo group of 4)
                const uint4* kq = (const uint4*)(sk2 + (cg * 9 + ki * 3) * 8);
#pragma unroll
                for (int gg = 0; gg < 2; gg++) {
                    uint4 k0 = kq[0 + gg];      // tap 0
                    uint4 k1 = kq[2 + gg];      // tap 1
                    uint4 k2 = kq[4 + gg];      // tap 2
                    uint32_t k0a[4] = {k0.x, k0.y, k0.z, k0.w};
                    uint32_t k1a[4] = {k1.x, k1.y, k1.z, k1.w};
                    uint32_t k2a[4] = {k2.x, k2.y, k2.z, k2.w};
#pragma unroll
                    for (int j = 0; j < 4; j++) {
                        const int oo = gg * 4 + j;
                        __half2 kk0 = u2h(k0a[j]);
                        __half2 kk1 = u2h(k1a[j]);
                        __half2 kk2 = u2h(k2a[j]);
                        __half2 a0 = acc0[oo], a1 = acc1[oo];
                        a0 = __hmax2(a0, __hadd2(O0, kk0));
                        a1 = __hmax2(a1, __hadd2(O1, kk0));
                        a0 = __hmax2(a0, __hadd2(E0, kk1));
                        a1 = __hmax2(a1, __hadd2(E1, kk1));
                        a0 = __hmax2(a0, __hadd2(O1, kk2));
                        a1 = __hmax2(a1, __hadd2(O2, kk2));
                        acc0[oo] = a0; acc1[oo] = a1;
                    }
                }
            }
        }
        if (have)
            stage_sts(g, bf ^ 1);   // safe: all warps passed this iter's barrier
    }

    // ---- write out: out[b][o_base+oo][h][wb..wb+3] ----
    const size_t obase = (((size_t)b * Oc + o_base) * Hc + h) * Wc + wb;
#pragma unroll
    for (int oo = 0; oo < OT; oo++) {
        float2 f0 = __half22float2(acc0[oo]);
        float2 f1 = __half22float2(acc1[oo]);
        *(float4*)(out + obase + (size_t)oo * Hc * Wc) =
            make_float4(f0.x, f0.y, f1.x, f1.y);
    }
}

extern "C" void kernel_launch(void* const* d_in, const int* in_sizes, int n_in,
                              void* d_out, int out_size)
{
    const float* x  = (const float*)d_in[0];   // [8,64,64,64]
    const float* k  = (const float*)d_in[1];   // [64,64,3,3]
    float* out      = (float*)d_out;           // [8,64,64,64]
    (void)in_sizes; (void)n_in; (void)out_size;

    maxplus_fp16_kernel<<<1024, 64>>>(x, k, out);
}

// round 13
// speedup vs baseline: 1.1208x; 1.1208x over previous
#include <cuda_runtime.h>
#include <cuda_fp16.h>
#include <math_constants.h>
#include <cstdint>

// Max-plus conv2d in fp16x2, two-kernel version.
// K1: convert x fp32 -> fp16 scratch (4MB device global).
// K2: R10 geometry (128 thr = 16wq x 8hl; thread = 4o x 4w = 8 half2 accs;
//     grid 1024 = 8ht x 16ot x 8b) with cp.async 3-deep ring staging of
//     fp16 x rows (CCH=4). Compute inner loop identical to R10.

constexpr int Cc  = 64;
constexpr int Hc  = 64;
constexpr int Wc  = 64;
constexpr int Oc  = 64;
constexpr int Bc  = 8;
constexpr int OT  = 4;
constexpr int HT  = 8;
constexpr int CCH = 4;
constexpr int NCH = Cc / CCH;            // 16 chunks
constexpr int XROWS = HT + 2;            // 10
constexpr int HR    = 80;                // halves per row (160B; col j = w + 8)
constexpr int BUFH  = CCH * XROWS * HR;  // 3200 halves per ring slot
constexpr int NBUF  = 3;
constexpr int SKH   = Cc * 9 * OT;       // 2304 half2 (dup'd taps)

__device__ __align__(16) __half g_xh[Bc * Cc * Hc * Wc];   // 4 MB scratch

__global__ __launch_bounds__(256)
void cvt_fp16_kernel(const float* __restrict__ x)
{
    int i = (blockIdx.x * 256 + threadIdx.x) * 4;   // 2M elements total
    float4 v = *(const float4*)(x + i);
    __half2 a = __floats2half2_rn(v.x, v.y);
    __half2 b = __floats2half2_rn(v.z, v.w);
    uint2 u;
    u.x = *reinterpret_cast<uint32_t*>(&a);
    u.y = *reinterpret_cast<uint32_t*>(&b);
    *reinterpret_cast<uint2*>(g_xh + i) = u;
}

__device__ __forceinline__ void cp16(uint32_t s, const __half* g) {
    asm volatile("cp.async.cg.shared.global [%0], [%1], 16;\n" :: "r"(s), "l"(g));
}
__device__ __forceinline__ void cp_commit() {
    asm volatile("cp.async.commit_group;\n" ::: "memory");
}
template <int N> __device__ __forceinline__ void cp_wait() {
    asm volatile("cp.async.wait_group %0;\n" :: "n"(N) : "memory");
}

__device__ __forceinline__ __half2 u2h(uint32_t u) {
    return *reinterpret_cast<__half2*>(&u);
}

__global__ __launch_bounds__(128, 7)
void maxplus_fp16_kernel(const float* __restrict__ gk,
                         float* __restrict__ out)
{
    __shared__ __align__(16) __half  sx[NBUF * BUFH];  // 19.2 KB
    __shared__ __align__(16) __half2 sk2[SKH];         // 9.2 KB

    const int bid = blockIdx.x;
    const int ht  = bid & 7;          // 8 h-tiles
    const int ot  = (bid >> 3) & 15;  // 16 o-tiles
    const int b   = bid >> 7;         // 8 batches

    const int h_base = ht * HT;
    const int o_base = ot * OT;

    const int tid = threadIdx.x;      // 0..127
    const int wq  = tid & 15;
    const int hl  = tid >> 4;         // 0..7
    const int wb  = wq * 4;
    const int h   = h_base + hl;

    const __half  NEGH = __float2half(-CUDART_INF_F);
    const __half2 NEG2 = __half2half2(NEGH);

    const uint32_t sx_u32 = (uint32_t)__cvta_generic_to_shared(sx);

    // ---- stage k taps once, duplicated: sk2[(c*9+ki*3+tap)*4+oo]=(k,k) ----
    for (int idx = tid; idx < SKH; idx += 128) {
        int oo   = idx & 3;
        int rest = idx >> 2;          // c*9 + ki*3 + tap (c global)
        sk2[idx] = __half2half2(__float2half_rn(gk[(o_base + oo) * (Cc * 9) + rest]));
    }

    // ---- prefill pads (cp.async never writes them), all NBUF slots ----
    // row content: col j = w + 8; valid w written at j=8..71.
    // pads read by compute: j=6,7 (w=-2,-1) and j=72,73 (w=64,65).
    for (int rw = tid; rw < NBUF * CCH * XROWS; rw += 128) {
        __half2* p = reinterpret_cast<__half2*>(sx + rw * HR + 6);
        p[0] = NEG2;                              // j 6,7
        __half2* q = reinterpret_cast<__half2*>(sx + rw * HR + 72);
        q[0] = NEG2;                              // j 72,73
    }
    // invalid h rows (ht==0 -> local row 0; ht==7 -> local row 9): interiors
    if (ht == 0 || ht == 7) {
        const int r = (ht == 0) ? 0 : (XROWS - 1);
        for (int i = tid; i < NBUF * CCH * 32; i += 128) {   // 32 half2 per row
            int j2 = i & 31;
            int cl = (i >> 5) & 3;
            int bf = i / (CCH * 32);
            *reinterpret_cast<__half2*>(
                sx + bf * BUFH + (cl * XROWS + r) * HR + 8 + j2 * 2) = NEG2;
        }
    }

    // ---- staging geometry: 320 cp16 per chunk; thread slots tid, +128, +256 ----
    const __half* xsrc = g_xh + (size_t)b * Cc * Hc * Wc;
    int  gof[3], dof[3];
    bool vr[3];
    const int nslot = (tid < 64) ? 3 : 2;
#pragma unroll
    for (int jj = 0; jj < 3; jj++) {
        int idx = tid + 128 * jj;
        if (idx < CCH * XROWS * 8) {
            int q  = idx & 7;            // 8 cp16 per row (128B interior)
            int rw = idx >> 3;           // cl*10 + r
            int r  = rw % XROWS;
            int cl = rw / XROWS;
            int hh = h_base - 1 + r;
            vr[jj]  = (hh >= 0 && hh < Hc);
            gof[jj] = (cl * Hc + (vr[jj] ? hh : 0)) * Wc + q * 8;
            dof[jj] = (rw * HR + 8 + q * 8) * 2;   // bytes
        } else { vr[jj] = false; gof[jj] = 0; dof[jj] = 0; }
    }

    auto stage = [&](int ch, int bf) {
        const __half* src = xsrc + (size_t)ch * CCH * Hc * Wc;
        const uint32_t dbase = sx_u32 + (uint32_t)(bf * BUFH * 2);
#pragma unroll
        for (int jj = 0; jj < 3; jj++)
            if (jj < nslot && vr[jj])
                cp16(dbase + dof[jj], src + gof[jj]);
    };

    // accumulators: acc0[oo]=(wb,wb+1), acc1[oo]=(wb+2,wb+3)
    __half2 acc0[OT], acc1[OT];
#pragma unroll
    for (int oo = 0; oo < OT; oo++) { acc0[oo] = NEG2; acc1[oo] = NEG2; }

    // ---- prologue: prefetch chunks 0,1 ----
    stage(0, 0); cp_commit();
    stage(1, 1); cp_commit();

    int bf = 0;
#pragma unroll 1
    for (int ch = 0; ch < NCH; ch++) {
        if (ch + 2 < NCH) cp_wait<1>();   // chunk ch complete (per-thread)
        else              cp_wait<0>();
        __syncthreads();                  // publish ch; prior readers of slot
                                          // (ch+2)%3 (= compute ch-1) are done
        if (ch + 2 < NCH) {
            int nb = bf + 2; if (nb >= NBUF) nb -= NBUF;
            stage(ch + 2, nb);
            cp_commit();
        }

        // ---- compute chunk ch from ring slot bf ----
        const __half* xb = sx + bf * BUFH;
#pragma unroll
        for (int cl = 0; cl < CCH; cl++) {
            const int cg = ch * CCH + cl;
#pragma unroll
            for (int ki = 0; ki < 3; ki++) {
                const __half* row = xb + (cl * XROWS + hl + ki) * HR;
                uint2    Eu = *(const uint2*)(row + wb + 8);     // (E0,E1)
                uint32_t Mu = *(const uint32_t*)(row + wb + 6);  // (x[wb-2],x[wb-1])
                uint32_t Nu = *(const uint32_t*)(row + wb + 12); // (x[wb+4],x[wb+5])
                uint32_t O0u = __byte_perm(Mu,   Eu.x, 0x5432);  // (x[wb-1],x[wb])
                uint32_t O1u = __byte_perm(Eu.x, Eu.y, 0x5432);  // (x[wb+1],x[wb+2])
                uint32_t O2u = __byte_perm(Eu.y, Nu,   0x5432);  // (x[wb+3],x[wb+4])
                __half2 E0 = u2h(Eu.x), E1 = u2h(Eu.y);
                __half2 O0 = u2h(O0u), O1 = u2h(O1u), O2 = u2h(O2u);

                const uint4* kp = (const uint4*)(sk2 + (cg * 9 + ki * 3) * 4);
                uint4 ka = kp[0];   // tap 0, oo 0..3
                uint4 kb = kp[1];   // tap 1
                uint4 kc = kp[2];   // tap 2
                uint32_t k0a[4] = {ka.x, ka.y, ka.z, ka.w};
                uint32_t k1a[4] = {kb.x, kb.y, kb.z, kb.w};
                uint32_t k2a[4] = {kc.x, kc.y, kc.z, kc.w};

#pragma unroll
                for (int oo = 0; oo < OT; oo++) {
                    __half2 k0 = u2h(k0a[oo]);
                    __half2 k1 = u2h(k1a[oo]);
                    __half2 k2 = u2h(k2a[oo]);
                    __half2 a0 = acc0[oo], a1 = acc1[oo];
                    a0 = __hmax2(a0, __hadd2(O0, k0));
                    a1 = __hmax2(a1, __hadd2(O1, k0));
                    a0 = __hmax2(a0, __hadd2(E0, k1));
                    a1 = __hmax2(a1, __hadd2(E1, k1));
                    a0 = __hmax2(a0, __hadd2(O1, k2));
                    a1 = __hmax2(a1, __hadd2(O2, k2));
                    acc0[oo] = a0; acc1[oo] = a1;
                }
            }
        }
        if (++bf >= NBUF) bf = 0;
    }

    // ---- write out: out[b][o_base+oo][h][wb..wb+3] ----
    const size_t obase = (((size_t)b * Oc + o_base) * Hc + h) * Wc + wb;
#pragma unroll
    for (int oo = 0; oo < OT; oo++) {
        float2 f0 = __half22float2(acc0[oo]);
        float2 f1 = __half22float2(acc1[oo]);
        *(float4*)(out + obase + (size_t)oo * Hc * Wc) =
            make_float4(f0.x, f0.y, f1.x, f1.y);
    }
}

extern "C" void kernel_launch(void* const* d_in, const int* in_sizes, int n_in,
                              void* d_out, int out_size)
{
    const float* x  = (const float*)d_in[0];   // [8,64,64,64]
    const float* k  = (const float*)d_in[1];   // [64,64,3,3]
    float* out      = (float*)d_out;           // [8,64,64,64]
    (void)in_sizes; (void)n_in; (void)out_size;

    // K1: x -> fp16 scratch (2M elems, 4 per thread, 256 thr/block)
    cvt_fp16_kernel<<<(Bc * Cc * Hc * Wc) / (4 * 256), 256>>>(x);
    // K2: main max-plus conv
    maxplus_fp16_kernel<<<1024, 128>>>(k, out);
}

// round 14
// speedup vs baseline: 1.1289x; 1.0072x over previous
#include <cuda_runtime.h>
#include <cuda_fp16.h>
#include <math_constants.h>
#include <cstdint>

// Max-plus conv2d in fp16x2, two-kernel version.
// K1: convert x fp32 -> fp16 scratch (4MB device global).
// K2: 128 thr = 16wq x 8hl; thread = 4o x 4w = 8 half2 accs; grid 1024.
//     cp.async 3-deep ring staging of fp16 x rows (CCH=4).
//     R14: compute loop flattened to 12 blocks with explicit 1-block
//     software pipeline (x words + k taps prefetched into registers),
//     so every LDS has >=48 issue slots before first use.

constexpr int Cc  = 64;
constexpr int Hc  = 64;
constexpr int Wc  = 64;
constexpr int Oc  = 64;
constexpr int Bc  = 8;
constexpr int OT  = 4;
constexpr int HT  = 8;
constexpr int CCH = 4;
constexpr int NCH = Cc / CCH;            // 16 chunks
constexpr int XROWS = HT + 2;            // 10
constexpr int HR    = 80;                // halves per row (160B; col j = w + 8)
constexpr int BUFH  = CCH * XROWS * HR;  // 3200 halves per ring slot
constexpr int NBUF  = 3;
constexpr int SKH   = Cc * 9 * OT;       // 2304 half2 (dup'd taps)

__device__ __align__(16) __half g_xh[Bc * Cc * Hc * Wc];   // 4 MB scratch

__global__ __launch_bounds__(256)
void cvt_fp16_kernel(const float* __restrict__ x)
{
    int i = (blockIdx.x * 256 + threadIdx.x) * 4;   // 2M elements total
    float4 v = *(const float4*)(x + i);
    __half2 a = __floats2half2_rn(v.x, v.y);
    __half2 b = __floats2half2_rn(v.z, v.w);
    uint2 u;
    u.x = *reinterpret_cast<uint32_t*>(&a);
    u.y = *reinterpret_cast<uint32_t*>(&b);
    *reinterpret_cast<uint2*>(g_xh + i) = u;
}

__device__ __forceinline__ void cp16(uint32_t s, const __half* g) {
    asm volatile("cp.async.cg.shared.global [%0], [%1], 16;\n" :: "r"(s), "l"(g));
}
__device__ __forceinline__ void cp_commit() {
    asm volatile("cp.async.commit_group;\n" ::: "memory");
}
template <int N> __device__ __forceinline__ void cp_wait() {
    asm volatile("cp.async.wait_group %0;\n" :: "n"(N) : "memory");
}

__device__ __forceinline__ __half2 u2h(uint32_t u) {
    return *reinterpret_cast<__half2*>(&u);
}

__global__ __launch_bounds__(128, 7)
void maxplus_fp16_kernel(const float* __restrict__ gk,
                         float* __restrict__ out)
{
    __shared__ __align__(16) __half  sx[NBUF * BUFH];  // 19.2 KB
    __shared__ __align__(16) __half2 sk2[SKH];         // 9.2 KB

    const int bid = blockIdx.x;
    const int ht  = bid & 7;          // 8 h-tiles
    const int ot  = (bid >> 3) & 15;  // 16 o-tiles
    const int b   = bid >> 7;         // 8 batches

    const int h_base = ht * HT;
    const int o_base = ot * OT;

    const int tid = threadIdx.x;      // 0..127
    const int wq  = tid & 15;
    const int hl  = tid >> 4;         // 0..7
    const int wb  = wq * 4;
    const int h   = h_base + hl;

    const __half  NEGH = __float2half(-CUDART_INF_F);
    const __half2 NEG2 = __half2half2(NEGH);

    const uint32_t sx_u32 = (uint32_t)__cvta_generic_to_shared(sx);

    // ---- stage k taps once, duplicated: sk2[(c*9+ki*3+tap)*4+oo]=(k,k) ----
    for (int idx = tid; idx < SKH; idx += 128) {
        int oo   = idx & 3;
        int rest = idx >> 2;          // c*9 + ki*3 + tap (c global)
        sk2[idx] = __half2half2(__float2half_rn(gk[(o_base + oo) * (Cc * 9) + rest]));
    }

    // ---- prefill pads (cp.async never writes them), all NBUF slots ----
    // row content: col j = w + 8; valid w written at j=8..71.
    // pads read by compute: j=6,7 (w=-2,-1) and j=72,73 (w=64,65).
    for (int rw = tid; rw < NBUF * CCH * XROWS; rw += 128) {
        *reinterpret_cast<__half2*>(sx + rw * HR + 6)  = NEG2;   // j 6,7
        *reinterpret_cast<__half2*>(sx + rw * HR + 72) = NEG2;   // j 72,73
    }
    // invalid h rows (ht==0 -> local row 0; ht==7 -> local row 9): interiors
    if (ht == 0 || ht == 7) {
        const int r = (ht == 0) ? 0 : (XROWS - 1);
        for (int i = tid; i < NBUF * CCH * 32; i += 128) {   // 32 half2 per row
            int j2 = i & 31;
            int cl = (i >> 5) & 3;
            int bf = i / (CCH * 32);
            *reinterpret_cast<__half2*>(
                sx + bf * BUFH + (cl * XROWS + r) * HR + 8 + j2 * 2) = NEG2;
        }
    }

    // ---- staging geometry: 320 cp16 per chunk; thread slots tid, +128, +256 ----
    const __half* xsrc = g_xh + (size_t)b * Cc * Hc * Wc;
    int  gof[3], dof[3];
    bool vr[3];
    const int nslot = (tid < 64) ? 3 : 2;
#pragma unroll
    for (int jj = 0; jj < 3; jj++) {
        int idx = tid + 128 * jj;
        if (idx < CCH * XROWS * 8) {
            int q  = idx & 7;            // 8 cp16 per row (128B interior)
            int rw = idx >> 3;           // cl*10 + r
            int r  = rw % XROWS;
            int cl = rw / XROWS;
            int hh = h_base - 1 + r;
            vr[jj]  = (hh >= 0 && hh < Hc);
            gof[jj] = (cl * Hc + (vr[jj] ? hh : 0)) * Wc + q * 8;
            dof[jj] = (rw * HR + 8 + q * 8) * 2;   // bytes
        } else { vr[jj] = false; gof[jj] = 0; dof[jj] = 0; }
    }

    auto stage = [&](int ch, int bf) {
        const __half* src = xsrc + (size_t)ch * CCH * Hc * Wc;
        const uint32_t dbase = sx_u32 + (uint32_t)(bf * BUFH * 2);
#pragma unroll
        for (int jj = 0; jj < 3; jj++)
            if (jj < nslot && vr[jj])
                cp16(dbase + dof[jj], src + gof[jj]);
    };

    // accumulators: acc0[oo]=(wb,wb+1), acc1[oo]=(wb+2,wb+3)
    __half2 acc0[OT], acc1[OT];
#pragma unroll
    for (int oo = 0; oo < OT; oo++) { acc0[oo] = NEG2; acc1[oo] = NEG2; }

    // ---- prologue: prefetch chunks 0,1 ----
    stage(0, 0); cp_commit();
    stage(1, 1); cp_commit();

    int bf = 0;
#pragma unroll 1
    for (int ch = 0; ch < NCH; ch++) {
        if (ch + 2 < NCH) cp_wait<1>();   // chunk ch complete (per-thread)
        else              cp_wait<0>();
        __syncthreads();                  // publish ch; prior readers of slot
                                          // (ch+2)%3 (= compute ch-1) are done
        if (ch + 2 < NCH) {
            int nb = bf + 2; if (nb >= NBUF) nb -= NBUF;
            stage(ch + 2, nb);
            cp_commit();
        }

        // ---- compute chunk ch from ring slot bf: 12 (cl,ki) blocks, ----
        // ---- explicit 1-block register pipeline for x words + k taps ----
        const __half*  xb  = sx + bf * BUFH;
        const __half2* skc = sk2 + (ch * CCH * 9) * 4;   // this chunk's taps

        uint2    Eu; uint32_t Mu, Nu;
        uint4    ka, kb, kc;
        {   // prime block t=0 (cl=0, ki=0)
            const __half* row = xb + hl * HR;
            Eu = *(const uint2*)(row + wb + 8);
            Mu = *(const uint32_t*)(row + wb + 6);
            Nu = *(const uint32_t*)(row + wb + 12);
            const uint4* kq = (const uint4*)skc;
            ka = kq[0]; kb = kq[1]; kc = kq[2];
        }

#pragma unroll
        for (int t = 0; t < 12; t++) {
            // -- prefetch block t+1 into fresh registers (compile-time guard) --
            uint2 EuN; uint32_t MuN, NuN; uint4 kaN, kbN, kcN;
            if (t < 11) {
                const int tn  = t + 1;
                const int cln = tn / 3, kin = tn % 3;
                const __half* rowN = xb + (cln * XROWS + hl + kin) * HR;
                EuN = *(const uint2*)(rowN + wb + 8);
                MuN = *(const uint32_t*)(rowN + wb + 6);
                NuN = *(const uint32_t*)(rowN + wb + 12);
                const uint4* kqN = (const uint4*)(skc + (cln * 9 + kin * 3) * 4);
                kaN = kqN[0]; kbN = kqN[1]; kcN = kqN[2];
            }

            // -- unpack + 48 packed arith for block t --
            uint32_t O0u = __byte_perm(Mu,   Eu.x, 0x5432);  // (x[wb-1],x[wb])
            uint32_t O1u = __byte_perm(Eu.x, Eu.y, 0x5432);  // (x[wb+1],x[wb+2])
            uint32_t O2u = __byte_perm(Eu.y, Nu,   0x5432);  // (x[wb+3],x[wb+4])
            __half2 E0 = u2h(Eu.x), E1 = u2h(Eu.y);
            __half2 O0 = u2h(O0u), O1 = u2h(O1u), O2 = u2h(O2u);

            uint32_t k0a[4] = {ka.x, ka.y, ka.z, ka.w};
            uint32_t k1a[4] = {kb.x, kb.y, kb.z, kb.w};
            uint32_t k2a[4] = {kc.x, kc.y, kc.z, kc.w};

#pragma unroll
            for (int oo = 0; oo < OT; oo++) {
                __half2 k0 = u2h(k0a[oo]);
                __half2 k1 = u2h(k1a[oo]);
                __half2 k2 = u2h(k2a[oo]);
                __half2 a0 = acc0[oo], a1 = acc1[oo];
                a0 = __hmax2(a0, __hadd2(O0, k0));
                a1 = __hmax2(a1, __hadd2(O1, k0));
                a0 = __hmax2(a0, __hadd2(E0, k1));
                a1 = __hmax2(a1, __hadd2(E1, k1));
                a0 = __hmax2(a0, __hadd2(O1, k2));
                a1 = __hmax2(a1, __hadd2(O2, k2));
                acc0[oo] = a0; acc1[oo] = a1;
            }

            if (t < 11) {
                Eu = EuN; Mu = MuN; Nu = NuN;
                ka = kaN; kb = kbN; kc = kcN;
            }
        }
        if (++bf >= NBUF) bf = 0;
    }

    // ---- write out: out[b][o_base+oo][h][wb..wb+3] ----
    const size_t obase = (((size_t)b * Oc + o_base) * Hc + h) * Wc + wb;
#pragma unroll
    for (int oo = 0; oo < OT; oo++) {
        float2 f0 = __half22float2(acc0[oo]);
        float2 f1 = __half22float2(acc1[oo]);
        *(float4*)(out + obase + (size_t)oo * Hc * Wc) =
            make_float4(f0.x, f0.y, f1.x, f1.y);
    }
}

extern "C" void kernel_launch(void* const* d_in, const int* in_sizes, int n_in,
                              void* d_out, int out_size)
{
    const float* x  = (const float*)d_in[0];   // [8,64,64,64]
    const float* k  = (const float*)d_in[1];   // [64,64,3,3]
    float* out      = (float*)d_out;           // [8,64,64,64]
    (void)in_sizes; (void)n_in; (void)out_size;

    // K1: x -> fp16 scratch (2M elems, 4 per thread, 256 thr/block)
    cvt_fp16_kernel<<<(Bc * Cc * Hc * Wc) / (4 * 256), 256>>>(x);
    // K2: main max-plus conv
    maxplus_fp16_kernel<<<1024, 128>>>(k, out);
}